// round 16
// baseline (speedup 1.0000x reference)
#include <cuda_runtime.h>
#include <cuda.h>
#include <cuda_fp16.h>
#include <cstdint>

#define KDIM 4096
#define ODIM 11008
#define KW   1376            // ODIM/8
#define BM 128
#define BN 128
#define NSTG 64              // KDIM/64

#define ASZ 16384            // 128 rows x 128B (64 f16)
#define STG 32768            // A + B per stage
#define MBAR_OFF 98304       // after 3 stages: full[3] then empty[3]
#define SMEM_TOTAL 98432

__device__ __half g_x16[(size_t)4096 * 4096];     // x as fp16, [M][K]
__device__ __half g_w16[(size_t)11008 * 4096];    // dequant weights fp16, [O][K]

// ---------------- pre-kernel 1: x fp32 -> fp16 ----------------
__global__ __launch_bounds__(256)
void cvt_x(const float* __restrict__ x) {
    size_t i = ((size_t)blockIdx.x * 256 + threadIdx.x) * 4;
    float4 v = *(const float4*)(x + i);
    __half2 h0 = __floats2half2_rn(v.x, v.y);
    __half2 h1 = __floats2half2_rn(v.z, v.w);
    uint2 u;
    u.x = *(unsigned*)&h0;
    u.y = *(unsigned*)&h1;
    *(uint2*)(g_x16 + i) = u;
}

// ------- pre-kernel 2: dequantize weights to fp16 [O][K] -------
__global__ __launch_bounds__(256)
void dequant_w(const int* __restrict__ qweight, const float* __restrict__ scales,
               const int* __restrict__ qzeros) {
    const int w  = blockIdx.x * 32 + (threadIdx.x & 31);
    const int kb = blockIdx.y * 8  + (threadIdx.x >> 5);
    const int g  = kb >> 3;

    int qw[16];
    #pragma unroll
    for (int i = 0; i < 16; i++)
        qw[i] = qweight[(size_t)(kb * 16 + i) * KW + w];
    const int zw = qzeros[(size_t)g * KW + w];
    const float4 s0 = *(const float4*)(scales + (size_t)g * ODIM + w * 8);
    const float4 s1 = *(const float4*)(scales + (size_t)g * ODIM + w * 8 + 4);
    const float sv[8] = {s0.x, s0.y, s0.z, s0.w, s1.x, s1.y, s1.z, s1.w};

    #pragma unroll
    for (int j = 0; j < 8; j++) {
        const int z = (zw >> (4 * j)) & 15;
        const float s = sv[j];
        unsigned u[8];
        #pragma unroll
        for (int p = 0; p < 8; p++) {
            float f0 = (float)(((qw[2 * p]     >> (4 * j)) & 15) - z) * s;
            float f1 = (float)(((qw[2 * p + 1] >> (4 * j)) & 15) - z) * s;
            __half2 h = __floats2half2_rn(f0, f1);
            u[p] = *(unsigned*)&h;
        }
        __half* dst = g_w16 + (size_t)(w * 8 + j) * KDIM + kb * 16;
        *(uint4*)dst       = make_uint4(u[0], u[1], u[2], u[3]);
        *(uint4*)(dst + 8) = make_uint4(u[4], u[5], u[6], u[7]);
    }
}

// ---------------- helpers ----------------
static __device__ __forceinline__ void ldsm_x4(unsigned* r, unsigned addr) {
    asm volatile("ldmatrix.sync.aligned.m8n8.x4.shared.b16 {%0,%1,%2,%3}, [%4];"
                 : "=r"(r[0]), "=r"(r[1]), "=r"(r[2]), "=r"(r[3]) : "r"(addr));
}
static __device__ __forceinline__ void mma_f16(float* c, const unsigned* a,
                                               const unsigned* b) {
    asm volatile(
        "mma.sync.aligned.m16n8k16.row.col.f32.f16.f16.f32 "
        "{%0,%1,%2,%3}, {%4,%5,%6,%7}, {%8,%9}, {%0,%1,%2,%3};"
        : "+f"(c[0]), "+f"(c[1]), "+f"(c[2]), "+f"(c[3])
        : "r"(a[0]), "r"(a[1]), "r"(a[2]), "r"(a[3]), "r"(b[0]), "r"(b[1]));
}
static __device__ __forceinline__ void mbar_wait(unsigned a, unsigned parity) {
    asm volatile(
        "{\n\t.reg .pred P;\n\t"
        "WL%=:\n\t"
        "mbarrier.try_wait.parity.acquire.cta.shared::cta.b64 P, [%0], %1, 0x989680;\n\t"
        "@P bra.uni WD%=;\n\t"
        "bra.uni WL%=;\n\t"
        "WD%=:\n\t}"
        :: "r"(a), "r"(parity) : "memory");
}
static __device__ __forceinline__ void mbar_arrive(unsigned a) {
    asm volatile("mbarrier.arrive.release.cta.shared::cta.b64 _, [%0];"
                 :: "r"(a) : "memory");
}

// -- main GEMM: 128 thr, 4 warps 2x2 (warp 64x64), TMA-fed, frag-pipelined --
__global__ __launch_bounds__(128, 2)
void w4_hgemm(const __grid_constant__ CUtensorMap tma_a,
              const __grid_constant__ CUtensorMap tma_b,
              float* __restrict__ out) {
    extern __shared__ __align__(1024) char smem[];
    unsigned sbase;
    asm("{ .reg .u64 t; cvta.to.shared.u64 t, %1; cvt.u32.u64 %0, t; }"
        : "=r"(sbase) : "l"(smem));
    const int tid  = threadIdx.x;
    const int lane = tid & 31;
    const int wid  = tid >> 5;
    const int wm   = wid >> 1;                 // 0..1  (64 rows)
    const int wn   = wid & 1;                  // 0..1  (64 cols)
    const int bm0  = blockIdx.x * BM;          // bm fast
    const int bn0  = blockIdx.y * BN;

    const unsigned FULL  = sbase + MBAR_OFF;        // 3 x 8B, count 1
    const unsigned EMPTY = sbase + MBAR_OFF + 24;   // 3 x 8B, count 4 (per-warp)

    if (tid == 0) {
        #pragma unroll
        for (int s = 0; s < 3; s++) {
            asm volatile("mbarrier.init.shared.b64 [%0], 1;"
                         :: "r"(FULL + s * 8) : "memory");
            asm volatile("mbarrier.init.shared.b64 [%0], 4;"
                         :: "r"(EMPTY + s * 8) : "memory");
        }
    }
    __syncthreads();

    auto issue = [&](int t) {                  // one thread: expect_tx + 2 TMA
        const int s = t % 3;
        const unsigned mb = FULL + s * 8;
        asm volatile("mbarrier.arrive.expect_tx.shared.b64 _, [%0], %1;"
                     :: "r"(mb), "r"((unsigned)STG) : "memory");
        asm volatile(
            "cp.async.bulk.tensor.2d.shared::cta.global.tile.mbarrier::complete_tx::bytes "
            "[%0], [%1, {%2, %3}], [%4];"
            :: "r"(sbase + s * STG), "l"(&tma_a), "r"(t * 64), "r"(bm0), "r"(mb)
            : "memory");
        asm volatile(
            "cp.async.bulk.tensor.2d.shared::cta.global.tile.mbarrier::complete_tx::bytes "
            "[%0], [%1, {%2, %3}], [%4];"
            :: "r"(sbase + s * STG + ASZ), "l"(&tma_b), "r"(t * 64), "r"(bn0), "r"(mb)
            : "memory");
    };
    if (tid == 0) { issue(0); issue(1); issue(2); }

    float acc[4][8][4];
    #pragma unroll
    for (int i = 0; i < 4; i++)
        #pragma unroll
        for (int j = 0; j < 8; j++)
            #pragma unroll
            for (int q = 0; q < 4; q++) acc[i][j][q] = 0.0f;

    const int arow = lane & 15;
    const int asel = lane >> 4;
    const int bg   = lane >> 3;                  // 0..3
    const int r = lane >> 2;
    const int c = lane & 3;

    #pragma unroll 1
    for (int t = 0; t < NSTG; t++) {
        const int s = t % 3;
        const unsigned par = (unsigned)((t / 3) & 1);
        mbar_wait(FULL + s * 8, par);            // own data dependency only

        const unsigned As = sbase + s * STG;
        const unsigned Bs = As + ASZ;

        // fragment register double-buffer: prefetch ks+1 while MMAing ks
        unsigned a[2][4][4], b[2][8][2];
        {   // load ks = 0
            #pragma unroll
            for (int mt = 0; mt < 4; mt++) {
                const int row = wm * 64 + mt * 16 + arow;
                ldsm_x4(a[0][mt], As + row * 128 + ((asel ^ (row & 7)) * 16));
            }
            #pragma unroll
            for (int p = 0; p < 4; p++) {
                const int n = wn * 64 + p * 16 + ((bg >> 1) << 3) + (lane & 7);
                ldsm_x4(&b[0][2 * p][0],
                        Bs + n * 128 + (((bg & 1) ^ (n & 7)) * 16));
            }
        }
        #pragma unroll
        for (int ks = 0; ks < 4; ks++) {
            const int cur = ks & 1;
            const int nxt = cur ^ 1;
            if (ks < 3) {                        // prefetch ks+1 fragments
                const int ch0 = 2 * (ks + 1);
                #pragma unroll
                for (int mt = 0; mt < 4; mt++) {
                    const int row = wm * 64 + mt * 16 + arow;
                    ldsm_x4(a[nxt][mt],
                            As + row * 128 + (((ch0 + asel) ^ (row & 7)) * 16));
                }
                #pragma unroll
                for (int p = 0; p < 4; p++) {
                    const int n = wn * 64 + p * 16 + ((bg >> 1) << 3) + (lane & 7);
                    ldsm_x4(&b[nxt][2 * p][0],
                            Bs + n * 128 + (((ch0 + (bg & 1)) ^ (n & 7)) * 16));
                }
            }
            #pragma unroll
            for (int mt = 0; mt < 4; mt++)
                #pragma unroll
                for (int nt = 0; nt < 8; nt++)
                    mma_f16(acc[mt][nt], a[cur][mt], b[cur][nt]);
        }

        __syncwarp();
        if (lane == 0) mbar_arrive(EMPTY + s * 8);   // warp done reading buffer s

        // round-robin issuer: each warp pays the EMPTY wait only every 4th stage
        if (t + 3 < NSTG && wid == (t & 3) && lane == 0) {
            mbar_wait(EMPTY + s * 8, par);           // all 4 warps released s
            issue(t + 3);                            // reuse buffer s
        }
    }

    // ---- epilogue: streaming stores (keep A/B resident in L2) ----
    #pragma unroll
    for (int mt = 0; mt < 4; mt++) {
        #pragma unroll
        for (int nt = 0; nt < 8; nt++) {
            const int row = bm0 + wm * 64 + mt * 16 + r;
            const int col = bn0 + wn * 64 + nt * 8 + c * 2;
            float* p = out + (size_t)row * ODIM + col;
            __stcs((float2*)p, make_float2(acc[mt][nt][0], acc[mt][nt][1]));
            __stcs((float2*)(p + (size_t)8 * ODIM),
                   make_float2(acc[mt][nt][2], acc[mt][nt][3]));
        }
    }
}

// Driver entry point fetched through cudart (no -lcuda needed at link time)
typedef CUresult (*PFN_encodeTiled)(
    CUtensorMap*, CUtensorMapDataType, cuuint32_t, void*,
    const cuuint64_t*, const cuuint64_t*, const cuuint32_t*, const cuuint32_t*,
    CUtensorMapInterleave, CUtensorMapSwizzle, CUtensorMapL2promotion,
    CUtensorMapFloatOOBfill);

extern "C" void kernel_launch(void* const* d_in, const int* in_sizes, int n_in,
                              void* d_out, int out_size) {
    const float* x       = (const float*)d_in[0];
    const int*   qweight = (const int*)d_in[1];
    const float* scales  = (const float*)d_in[2];
    const int*   qzeros  = (const int*)d_in[3];
    float*       out     = (float*)d_out;

    const int M = in_sizes[0] / KDIM;            // 4096

    cvt_x<<<(M * KDIM) / (256 * 4), 256>>>(x);
    dequant_w<<<dim3(KW / 32, 32), 256>>>(qweight, scales, qzeros);

    static CUtensorMap tma_a, tma_b;
    static bool built = false;
    if (!built) {
        PFN_encodeTiled encode = nullptr;
        cudaDriverEntryPointQueryResult qr;
#if CUDART_VERSION >= 12050
        cudaGetDriverEntryPointByVersion("cuTensorMapEncodeTiled",
                                         (void**)&encode, 12000,
                                         cudaEnableDefault, &qr);
#else
        cudaGetDriverEntryPoint("cuTensorMapEncodeTiled",
                                (void**)&encode, cudaEnableDefault, &qr);
#endif
        void *pa = nullptr, *pb = nullptr;
        cudaGetSymbolAddress(&pa, g_x16);
        cudaGetSymbolAddress(&pb, g_w16);
        cuuint64_t dims_a[2] = {(cuuint64_t)KDIM, (cuuint64_t)M};
        cuuint64_t dims_b[2] = {(cuuint64_t)KDIM, (cuuint64_t)ODIM};
        cuuint64_t strides[1] = {(cuuint64_t)KDIM * 2};
        cuuint32_t box[2] = {64, 128};
        cuuint32_t es[2] = {1, 1};
        encode(&tma_a, CU_TENSOR_MAP_DATA_TYPE_UINT16, 2, pa,
               dims_a, strides, box, es,
               CU_TENSOR_MAP_INTERLEAVE_NONE, CU_TENSOR_MAP_SWIZZLE_128B,
               CU_TENSOR_MAP_L2_PROMOTION_L2_128B, CU_TENSOR_MAP_FLOAT_OOB_FILL_NONE);
        encode(&tma_b, CU_TENSOR_MAP_DATA_TYPE_UINT16, 2, pb,
               dims_b, strides, box, es,
               CU_TENSOR_MAP_INTERLEAVE_NONE, CU_TENSOR_MAP_SWIZZLE_128B,
               CU_TENSOR_MAP_L2_PROMOTION_L2_128B, CU_TENSOR_MAP_FLOAT_OOB_FILL_NONE);
        built = true;
    }

    cudaFuncSetAttribute(w4_hgemm, cudaFuncAttributeMaxDynamicSharedMemorySize,
                         SMEM_TOTAL);
    dim3 grid(M / BM, ODIM / BN);                // (32, 86) — bm fast
    w4_hgemm<<<grid, 128, SMEM_TOTAL>>>(tma_a, tma_b, out);
}